// round 3
// baseline (speedup 1.0000x reference)
#include <cuda_runtime.h>
#include <cuda_bf16.h>
#include <cstdint>

// Problem dims (fixed by the dataset)
#define BB 32
#define SS 1024
#define II 256
#define HH 512
#define OO 256
#define MROWS (BB * SS)   // 32768
#define CSZ 4             // cluster size (CTAs per batch)
#define HSL (HH / CSZ)    // 128 h-columns per CTA

// Scratch (allocation-free rule: __device__ globals)
__device__ float g_ic[(size_t)MROWS * HH];   // 64 MB input currents
__device__ float g_spk[(size_t)MROWS * HH];  // 64 MB spikes (fp32 0/1)

// ---------------------------------------------------------------------------
// Register-blocked SGEMM: C[M,N] = A[M,K] @ B[K,N], all row-major fp32.
// ---------------------------------------------------------------------------
template <int BM, int BN, int BK, int TM, int TN>
__global__ __launch_bounds__(256) void sgemm_kernel(
    const float* __restrict__ A, const float* __restrict__ Bm,
    float* __restrict__ C, int M, int N, int K)
{
    __shared__ float As[BK][BM];
    __shared__ float Bs[BK][BN];

    const int tid = threadIdx.x;
    const int mBlock = blockIdx.y * BM;
    const int nBlock = blockIdx.x * BN;

    const int tCols = BN / TN;
    const int tRow = tid / tCols;
    const int tCol = tid % tCols;

    float acc[TM][TN];
#pragma unroll
    for (int i = 0; i < TM; i++)
#pragma unroll
        for (int j = 0; j < TN; j++) acc[i][j] = 0.f;

    for (int k0 = 0; k0 < K; k0 += BK) {
#pragma unroll
        for (int it = 0; it < (BM * BK) / (256 * 4); it++) {
            int f = tid + it * 256;
            int m = f / (BK / 4);
            int kq = f % (BK / 4);
            float4 v = *reinterpret_cast<const float4*>(
                &A[(size_t)(mBlock + m) * K + k0 + kq * 4]);
            As[kq * 4 + 0][m] = v.x;
            As[kq * 4 + 1][m] = v.y;
            As[kq * 4 + 2][m] = v.z;
            As[kq * 4 + 3][m] = v.w;
        }
#pragma unroll
        for (int it = 0; it < (BK * BN) / (256 * 4); it++) {
            int f = tid + it * 256;
            int k = f / (BN / 4);
            int nq = f % (BN / 4);
            float4 v = *reinterpret_cast<const float4*>(
                &Bm[(size_t)(k0 + k) * N + nBlock + nq * 4]);
            *reinterpret_cast<float4*>(&Bs[k][nq * 4]) = v;
        }
        __syncthreads();

#pragma unroll
        for (int k = 0; k < BK; k++) {
            float ra[TM], rb[TN];
#pragma unroll
            for (int i = 0; i < TM; i++) ra[i] = As[k][tRow * TM + i];
#pragma unroll
            for (int j = 0; j < TN; j++) rb[j] = Bs[k][tCol * TN + j];
#pragma unroll
            for (int i = 0; i < TM; i++)
#pragma unroll
                for (int j = 0; j < TN; j++) acc[i][j] += ra[i] * rb[j];
        }
        __syncthreads();
    }

#pragma unroll
    for (int i = 0; i < TM; i++) {
        float* crow = &C[(size_t)(mBlock + tRow * TM + i) * N + nBlock + tCol * TN];
#pragma unroll
        for (int j = 0; j < TN; j += 4) {
            float4 v = make_float4(acc[i][j], acc[i][j + 1], acc[i][j + 2], acc[i][j + 3]);
            *reinterpret_cast<float4*>(&crow[j]) = v;
        }
    }
}

// ---------------------------------------------------------------------------
// Cluster-parallel recurrent scan.
// One 4-CTA cluster per batch; each CTA owns 128 neurons (one per thread) and
// gathers only its 128-column slice of W_lat rows for the firing set.
// Spike masks (4 ballot words per CTA) are exchanged through DSMEM into a
// double-buffered slot; one cluster.sync per step orders write(t) -> read(t),
// and the sync at t+1 separates read(t) from write(t+2) on the same buffer.
// ---------------------------------------------------------------------------
__device__ __forceinline__ uint32_t smem_addr_u32(const void* p) {
    uint32_t a;
    asm("{ .reg .u64 t; cvta.to.shared.u64 t, %1; cvt.u32.u64 %0, t; }"
        : "=r"(a) : "l"(p));
    return a;
}

__device__ __forceinline__ void st_shared_cluster_u32(uint32_t local_addr,
                                                      uint32_t target_rank,
                                                      uint32_t val) {
    asm volatile(
        "{ .reg .b32 r; mapa.shared::cluster.u32 r, %0, %1; "
        "st.shared::cluster.u32 [r], %2; }"
        :: "r"(local_addr), "r"(target_rank), "r"(val) : "memory");
}

__global__ void __cluster_dims__(CSZ, 1, 1) __launch_bounds__(128, 1)
snn_scan_cluster_kernel(
    const float* __restrict__ ic, const float* __restrict__ Wlat,
    const float* __restrict__ thr, float* __restrict__ spk)
{
    __shared__ unsigned masks_s[2][CSZ * 4];  // [buf][rank*4 + word]
    __shared__ int list_s[HH];

    const int tid = threadIdx.x;           // 0..127
    const int lane = tid & 31;
    const int warp = tid >> 5;             // 0..3
    const int b = blockIdx.x / CSZ;
    uint32_t rank;
    asm("mov.u32 %0, %%cluster_ctarank;" : "=r"(rank));

    const int h = (int)rank * HSL + tid;   // this thread's neuron
    const float thrv = thr[h];

    float mp = 0.f;
    int refrac = 0;
    int ns = 0;

    const size_t rowbase = (size_t)b * SS * HH;
    float ic_cur = ic[rowbase + h];

    for (int t = 0; t < SS; ++t) {
        float ic_nxt = (t < SS - 1) ? ic[rowbase + (size_t)(t + 1) * HH + h] : 0.f;

        // --- lateral: sum this CTA's column-slice over the firing list ---
        float a0 = 0.f, a1 = 0.f, a2 = 0.f, a3 = 0.f;
        const float* Wcol = Wlat + (size_t)rank * HSL + tid;
        int k = 0;
        for (; k + 3 < ns; k += 4) {
            int j0 = list_s[k], j1 = list_s[k + 1];
            int j2 = list_s[k + 2], j3 = list_s[k + 3];
            a0 += Wcol[(size_t)j0 * HH];
            a1 += Wcol[(size_t)j1 * HH];
            a2 += Wcol[(size_t)j2 * HH];
            a3 += Wcol[(size_t)j3 * HH];
        }
        for (; k < ns; ++k) a0 += Wcol[(size_t)list_s[k] * HH];
        float lat = (a0 + a1) + (a2 + a3);

        // --- membrane update (reference semantics, fp32) ---
        mp = 0.95f * mp + ic_cur - lat;
        if (refrac > 0) mp = 0.f;
        refrac = (refrac > 0) ? (refrac - 1) : 0;
        bool spike = (mp >= thrv);
        spk[rowbase + (size_t)t * HH + h] = spike ? 1.f : 0.f;
        if (spike) { mp = 0.f; refrac = 2; }

        // --- broadcast my warp's ballot word to all 4 CTAs (buf = t&1) ---
        unsigned m = __ballot_sync(0xffffffffu, spike);
        const int buf = t & 1;
        if (lane == 0) {
            uint32_t laddr = smem_addr_u32(&masks_s[buf][rank * 4 + warp]);
#pragma unroll
            for (uint32_t r = 0; r < CSZ; ++r)
                st_shared_cluster_u32(laddr, r, m);
        }

        // --- cluster barrier: all mask writes of step t now visible ---
        asm volatile("barrier.cluster.arrive.aligned;" ::: "memory");
        asm volatile("barrier.cluster.wait.aligned;" ::: "memory");

        // --- rebuild full 512-neuron firing list from the 16 mask words ---
        unsigned w0[16];
        int pref[16];
        int tot = 0;
#pragma unroll
        for (int w = 0; w < 16; ++w) {
            w0[w] = masks_s[buf][w];
            pref[w] = tot;
            tot += __popc(w0[w]);
        }
#pragma unroll
        for (int q = 0; q < 4; ++q) {
            int j = tid + q * 128;
            int wd = j >> 5, bt = j & 31;
            unsigned mw = w0[wd];
            if (mw & (1u << bt)) {
                int pos = pref[wd] + __popc(mw & ((1u << bt) - 1u));
                list_s[pos] = j;
            }
        }
        ns = tot;
        ic_cur = ic_nxt;
        __syncthreads();   // list_s fully written before next gather
    }
}

// ---------------------------------------------------------------------------
// Launch
// ---------------------------------------------------------------------------
extern "C" void kernel_launch(void* const* d_in, const int* in_sizes, int n_in,
                              void* d_out, int out_size)
{
    const float* x    = (const float*)d_in[0];  // [B,S,I]
    const float* Win  = (const float*)d_in[1];  // [I,H]
    const float* Wlat = (const float*)d_in[2];  // [H,H]
    const float* Wout = (const float*)d_in[3];  // [H,O]
    const float* thr  = (const float*)d_in[4];  // [H]
    float* out = (float*)d_out;                 // [B,S,O]

    float *ic, *spk;
    cudaGetSymbolAddress((void**)&ic, g_ic);
    cudaGetSymbolAddress((void**)&spk, g_spk);

    // GEMM1: ic = x @ Win   (32768 x 512 x 256)
    {
        dim3 grid(HH / 64, MROWS / 128);
        sgemm_kernel<128, 64, 16, 8, 4><<<grid, 256>>>(x, Win, ic, MROWS, HH, II);
    }

    // Cluster-parallel scan: 32 clusters x 4 CTAs x 128 threads
    snn_scan_cluster_kernel<<<BB * CSZ, 128>>>(ic, Wlat, thr, spk);

    // GEMM3: out = spk @ Wout   (32768 x 256 x 512)
    {
        dim3 grid(OO / 64, MROWS / 128);
        sgemm_kernel<128, 64, 16, 8, 4><<<grid, 256>>>(spk, Wout, out, MROWS, OO, HH);
    }
}